// round 6
// baseline (speedup 1.0000x reference)
#include <cuda_runtime.h>
#include <cstdint>
#include <math.h>

// Problem constants (fixed by the dataset)
#define NS 100000
#define NE 100000
#define EDG 1600000
#define D 256
#define H 8
#define HD 32
#define FEAT 64
#define DFF 512

#define SCAN_B 1024
#define NBLK ((NS + SCAN_B - 1) / SCAN_B)   // 98

// ---------------- device scratch (no allocations allowed) ----------------
__device__ float g_z[(size_t)NE * D];
__device__ float g_df[(size_t)NS * D];
__device__ float g_h[(size_t)NS * D];
__device__ float g_x[(size_t)NS * D];
__device__ float g_xn[(size_t)NS * D];
__device__ float g_t[(size_t)NS * DFF];
__device__ float g_Wz[D * D];
__device__ float g_Wd[FEAT * D];
__device__ int   g_counts[NS];
__device__ int   g_offsets[NS + 1];
__device__ int   g_cursor[NS];
__device__ int   g_csr_src[EDG];
__device__ int   g_bsum[NBLK];

// ---------------- small helpers ----------------
__device__ __forceinline__ float gelu_fast(float x) {
    // tanh-approx gelu via exp (matches jax.nn.gelu default to ~1e-7)
    const float c = 0.7978845608028654f;
    float u = c * (x + 0.044715f * x * x * x);
    float e = __expf(2.0f * u);
    float th = 1.0f - 2.0f / (e + 1.0f);
    return 0.5f * x * (1.0f + th);
}

// 256-bit L2 evict_last gather load (keep z resident in L2).
// ptxas on this toolchain only allows evict_last with .v8.b32 / .v4.b64.
__device__ __forceinline__ void ldg_keep8(const float* p, float4& a, float4& b) {
    uint32_t r0, r1, r2, r3, r4, r5, r6, r7;
    asm volatile("ld.global.nc.L2::evict_last.v8.b32 {%0,%1,%2,%3,%4,%5,%6,%7}, [%8];"
                 : "=r"(r0), "=r"(r1), "=r"(r2), "=r"(r3),
                   "=r"(r4), "=r"(r5), "=r"(r6), "=r"(r7)
                 : "l"(p));
    a.x = __uint_as_float(r0); a.y = __uint_as_float(r1);
    a.z = __uint_as_float(r2); a.w = __uint_as_float(r3);
    b.x = __uint_as_float(r4); b.y = __uint_as_float(r5);
    b.z = __uint_as_float(r6); b.w = __uint_as_float(r7);
}

// ---------------- weight repack: (H, K, HD) -> [K, H*HD] ----------------
__global__ void repack_w(const float* __restrict__ w, float* __restrict__ out, int K) {
    int idx = blockIdx.x * blockDim.x + threadIdx.x;
    if (idx >= K * 256) return;
    int k = idx >> 8;
    int n = idx & 255;
    out[idx] = w[(n >> 5) * (K * 32) + k * 32 + (n & 31)];
}

// ---------------- generic fp32 SGEMM: C = act(A @ B + bias) + res ----------------
template <int ACT, bool HAS_BIAS, bool HAS_RES>
__global__ void __launch_bounds__(256) sgemm_k(
    const float* __restrict__ A0, int lda0,
    const float* __restrict__ A1, int lda1, int ksplit,
    const float* __restrict__ B,
    const float* __restrict__ bias,
    const float* __restrict__ res, int ldr,
    float* __restrict__ C,
    int M, int N, int K)
{
    __shared__ float As[8][132];
    __shared__ float Bs[8][128];

    int t  = threadIdx.x;
    int m0 = blockIdx.y * 128;
    int n0 = blockIdx.x * 128;
    int tx = t & 15;
    int ty = t >> 4;

    int a_m = t >> 1;
    int a_k = (t & 1) * 4;
    int b_k = t >> 5;
    int b_n = (t & 31) * 4;

    float acc[8][8];
#pragma unroll
    for (int i = 0; i < 8; i++)
#pragma unroll
        for (int j = 0; j < 8; j++) acc[i][j] = 0.0f;

    for (int k0 = 0; k0 < K; k0 += 8) {
        int gm = m0 + a_m;
        float4 av = make_float4(0.f, 0.f, 0.f, 0.f);
        if (gm < M) {
            int kk = k0 + a_k;
            const float* p = (kk < ksplit)
                                 ? (A0 + (size_t)gm * lda0 + kk)
                                 : (A1 + (size_t)gm * lda1 + (kk - ksplit));
            av = *(const float4*)p;
        }
        As[a_k + 0][a_m] = av.x;
        As[a_k + 1][a_m] = av.y;
        As[a_k + 2][a_m] = av.z;
        As[a_k + 3][a_m] = av.w;

        float4 bv = *(const float4*)(B + (size_t)(k0 + b_k) * N + n0 + b_n);
        *(float4*)&Bs[b_k][b_n] = bv;

        __syncthreads();

#pragma unroll
        for (int kk = 0; kk < 8; kk++) {
            float a[8], b[8];
            *(float4*)(a)     = *(const float4*)&As[kk][ty * 8];
            *(float4*)(a + 4) = *(const float4*)&As[kk][ty * 8 + 4];
            *(float4*)(b)     = *(const float4*)&Bs[kk][tx * 8];
            *(float4*)(b + 4) = *(const float4*)&Bs[kk][tx * 8 + 4];
#pragma unroll
            for (int i = 0; i < 8; i++)
#pragma unroll
                for (int j = 0; j < 8; j++) acc[i][j] += a[i] * b[j];
        }
        __syncthreads();
    }

#pragma unroll
    for (int i = 0; i < 8; i++) {
        int m = m0 + ty * 8 + i;
        if (m >= M) continue;
#pragma unroll
        for (int jv = 0; jv < 2; jv++) {
            int n = n0 + tx * 8 + jv * 4;
            float4 v;
            float* vp = &v.x;
#pragma unroll
            for (int j = 0; j < 4; j++) {
                float val = acc[i][jv * 4 + j];
                if (HAS_BIAS) val += bias[n + j];
                if (ACT == 1) val = gelu_fast(val);
                vp[j] = val;
            }
            if (HAS_RES) {
                float4 r = *(const float4*)(res + (size_t)m * ldr + n);
                v.x += r.x; v.y += r.y; v.z += r.z; v.w += r.w;
            }
            *(float4*)(C + (size_t)m * N + n) = v;
        }
    }
}

// ---------------- CSR build ----------------
__global__ void zero_counts() {
    int i = blockIdx.x * blockDim.x + threadIdx.x;
    if (i < NS) g_counts[i] = 0;
}
__global__ void hist_kernel(const int* __restrict__ edge_dst) {
    int i = blockIdx.x * blockDim.x + threadIdx.x;
    if (i < EDG) atomicAdd(&g_counts[edge_dst[i]], 1);
}
__global__ void __launch_bounds__(SCAN_B) scan_pass1() {
    __shared__ int ws[32];
    int b = blockIdx.x, t = threadIdx.x;
    int i = b * SCAN_B + t;
    int v = (i < NS) ? g_counts[i] : 0;
#pragma unroll
    for (int o = 16; o; o >>= 1) v += __shfl_xor_sync(0xFFFFFFFFu, v, o);
    if ((t & 31) == 0) ws[t >> 5] = v;
    __syncthreads();
    if (t < 32) {
        int x = ws[t];
#pragma unroll
        for (int o = 16; o; o >>= 1) x += __shfl_xor_sync(0xFFFFFFFFu, x, o);
        if (t == 0) g_bsum[b] = x;
    }
}
__global__ void scan_pass2() {
    __shared__ int sh[128];
    int t = threadIdx.x;
    int orig = (t < NBLK) ? g_bsum[t] : 0;
    sh[t] = orig;
    __syncthreads();
    for (int o = 1; o < 128; o <<= 1) {
        int v = (t >= o) ? sh[t - o] : 0;
        __syncthreads();
        sh[t] += v;
        __syncthreads();
    }
    if (t < NBLK) g_bsum[t] = sh[t] - orig;
}
__global__ void __launch_bounds__(SCAN_B) scan_pass3() {
    __shared__ int ws[32];
    int b = blockIdx.x, t = threadIdx.x;
    int lane = t & 31, w = t >> 5;
    int i = b * SCAN_B + t;
    int v = (i < NS) ? g_counts[i] : 0;
    int x = v;
#pragma unroll
    for (int o = 1; o < 32; o <<= 1) {
        int y = __shfl_up_sync(0xFFFFFFFFu, x, o);
        if (lane >= o) x += y;
    }
    if (lane == 31) ws[w] = x;
    __syncthreads();
    if (w == 0) {
        int sv = ws[lane];
#pragma unroll
        for (int o = 1; o < 32; o <<= 1) {
            int y = __shfl_up_sync(0xFFFFFFFFu, sv, o);
            if (lane >= o) sv += y;
        }
        ws[lane] = sv;
    }
    __syncthreads();
    int incl = x + (w > 0 ? ws[w - 1] : 0) + g_bsum[b];
    if (i < NS) {
        g_offsets[i + 1] = incl;
        g_cursor[i] = incl - v;
    }
    if (b == 0 && t == 0) g_offsets[0] = 0;
}
__global__ void scatter_kernel(const int* __restrict__ edge_src,
                               const int* __restrict__ edge_dst) {
    int i = blockIdx.x * blockDim.x + threadIdx.x;
    if (i >= EDG) return;
    int dst = edge_dst[i];
    int pos = atomicAdd(&g_cursor[dst], 1);
    g_csr_src[pos] = edge_src[i];
}

// ---------------- attention: warp per dst, lane = (head, quarter) ----------------
// z gather uses 256-bit L2::evict_last loads; df/h streams use evict-first so z
// stays L2-resident. 4-edge batched online softmax: one rescale + 5 exp per 4 edges.
__global__ void __launch_bounds__(256) attn_kernel() {
    int gw = (blockIdx.x * blockDim.x + threadIdx.x) >> 5;
    if (gw >= NS) return;
    int lane = threadIdx.x & 31;
    int off = (lane >> 2) * 32 + (lane & 3) * 8;  // base column for this lane

    int beg = g_offsets[gw];
    int end = g_offsets[gw + 1];

    const float* dfp = g_df + (size_t)gw * 256 + off;
    float4 d0 = __ldcs((const float4*)dfp);
    float4 d1 = __ldcs((const float4*)(dfp + 4));

    float m = -1e30f, den = 0.0f;
    float4 a0 = make_float4(0.f, 0.f, 0.f, 0.f);
    float4 a1 = make_float4(0.f, 0.f, 0.f, 0.f);

    int e = beg;
    for (; e + 4 <= end; e += 4) {
        int i0 = __ldg(&g_csr_src[e + 0]);
        int i1 = __ldg(&g_csr_src[e + 1]);
        int i2 = __ldg(&g_csr_src[e + 2]);
        int i3 = __ldg(&g_csr_src[e + 3]);
        float4 x0, x1, y0, y1, u0, u1, v0, v1;
        ldg_keep8(g_z + (size_t)i0 * 256 + off, x0, x1);
        ldg_keep8(g_z + (size_t)i1 * 256 + off, y0, y1);
        ldg_keep8(g_z + (size_t)i2 * 256 + off, u0, u1);
        ldg_keep8(g_z + (size_t)i3 * 256 + off, v0, v1);

        float s0 = x0.x * d0.x + x0.y * d0.y + x0.z * d0.z + x0.w * d0.w
                 + x1.x * d1.x + x1.y * d1.y + x1.z * d1.z + x1.w * d1.w;
        float s1 = y0.x * d0.x + y0.y * d0.y + y0.z * d0.z + y0.w * d0.w
                 + y1.x * d1.x + y1.y * d1.y + y1.z * d1.z + y1.w * d1.w;
        float s2 = u0.x * d0.x + u0.y * d0.y + u0.z * d0.z + u0.w * d0.w
                 + u1.x * d1.x + u1.y * d1.y + u1.z * d1.z + u1.w * d1.w;
        float s3 = v0.x * d0.x + v0.y * d0.y + v0.z * d0.z + v0.w * d0.w
                 + v1.x * d1.x + v1.y * d1.y + v1.z * d1.z + v1.w * d1.w;
        s0 += __shfl_xor_sync(0xFFFFFFFFu, s0, 1);
        s1 += __shfl_xor_sync(0xFFFFFFFFu, s1, 1);
        s2 += __shfl_xor_sync(0xFFFFFFFFu, s2, 1);
        s3 += __shfl_xor_sync(0xFFFFFFFFu, s3, 1);
        s0 += __shfl_xor_sync(0xFFFFFFFFu, s0, 2);
        s1 += __shfl_xor_sync(0xFFFFFFFFu, s1, 2);
        s2 += __shfl_xor_sync(0xFFFFFFFFu, s2, 2);
        s3 += __shfl_xor_sync(0xFFFFFFFFu, s3, 2);

        float mn = fmaxf(fmaxf(fmaxf(m, s0), fmaxf(s1, s2)), s3);
        float sc = __expf(m - mn);
        float w0 = __expf(s0 - mn);
        float w1 = __expf(s1 - mn);
        float w2 = __expf(s2 - mn);
        float w3 = __expf(s3 - mn);
        den = den * sc + (w0 + w1) + (w2 + w3);
        a0.x = a0.x * sc + w0 * x0.x + w1 * y0.x + w2 * u0.x + w3 * v0.x;
        a0.y = a0.y * sc + w0 * x0.y + w1 * y0.y + w2 * u0.y + w3 * v0.y;
        a0.z = a0.z * sc + w0 * x0.z + w1 * y0.z + w2 * u0.z + w3 * v0.z;
        a0.w = a0.w * sc + w0 * x0.w + w1 * y0.w + w2 * u0.w + w3 * v0.w;
        a1.x = a1.x * sc + w0 * x1.x + w1 * y1.x + w2 * u1.x + w3 * v1.x;
        a1.y = a1.y * sc + w0 * x1.y + w1 * y1.y + w2 * u1.y + w3 * v1.y;
        a1.z = a1.z * sc + w0 * x1.z + w1 * y1.z + w2 * u1.z + w3 * v1.z;
        a1.w = a1.w * sc + w0 * x1.w + w1 * y1.w + w2 * u1.w + w3 * v1.w;
        m = mn;
    }
    // tail
    for (; e < end; e++) {
        int i0 = __ldg(&g_csr_src[e]);
        float4 x0, x1;
        ldg_keep8(g_z + (size_t)i0 * 256 + off, x0, x1);
        float s0 = x0.x * d0.x + x0.y * d0.y + x0.z * d0.z + x0.w * d0.w
                 + x1.x * d1.x + x1.y * d1.y + x1.z * d1.z + x1.w * d1.w;
        s0 += __shfl_xor_sync(0xFFFFFFFFu, s0, 1);
        s0 += __shfl_xor_sync(0xFFFFFFFFu, s0, 2);
        float mn = fmaxf(m, s0);
        float sc = __expf(m - mn);
        float w0 = __expf(s0 - mn);
        den = den * sc + w0;
        a0.x = a0.x * sc + w0 * x0.x; a0.y = a0.y * sc + w0 * x0.y;
        a0.z = a0.z * sc + w0 * x0.z; a0.w = a0.w * sc + w0 * x0.w;
        a1.x = a1.x * sc + w0 * x1.x; a1.y = a1.y * sc + w0 * x1.y;
        a1.z = a1.z * sc + w0 * x1.z; a1.w = a1.w * sc + w0 * x1.w;
        m = mn;
    }

    float inv = 1.0f / den;
    float v[8];
    v[0] = a0.x * inv; v[1] = a0.y * inv; v[2] = a0.z * inv; v[3] = a0.w * inv;
    v[4] = a1.x * inv; v[5] = a1.y * inv; v[6] = a1.z * inv; v[7] = a1.w * inv;
#pragma unroll
    for (int i = 0; i < 8; i++)
        v[i] = (v[i] > 0.0f) ? v[i] : expm1f(v[i]);  // ELU(alpha=1)

    float* hp = g_h + (size_t)gw * 256 + off;
    __stcs((float4*)hp,       make_float4(v[0], v[1], v[2], v[3]));
    __stcs((float4*)(hp + 4), make_float4(v[4], v[5], v[6], v[7]));
}

// ---------------- layernorm: one warp per row ----------------
__global__ void ln_kernel(const float* __restrict__ x,
                          const float* __restrict__ gam,
                          const float* __restrict__ bet,
                          float* __restrict__ y) {
    int row = (blockIdx.x * blockDim.x + threadIdx.x) >> 5;
    if (row >= NS) return;
    int lane = threadIdx.x & 31;
    const float* xp = x + (size_t)row * 256;
    float v[8];
    float s = 0.0f, s2 = 0.0f;
#pragma unroll
    for (int r = 0; r < 8; r++) {
        v[r] = xp[r * 32 + lane];
        s += v[r];
        s2 += v[r] * v[r];
    }
#pragma unroll
    for (int off = 16; off > 0; off >>= 1) {
        s  += __shfl_xor_sync(0xFFFFFFFFu, s, off);
        s2 += __shfl_xor_sync(0xFFFFFFFFu, s2, off);
    }
    float mean = s * (1.0f / 256.0f);
    float var = s2 * (1.0f / 256.0f) - mean * mean;
    float inv = rsqrtf(var + 1e-6f);
    float* yp = y + (size_t)row * 256;
#pragma unroll
    for (int r = 0; r < 8; r++) {
        int c = r * 32 + lane;
        yp[c] = (v[r] - mean) * inv * gam[c] + bet[c];
    }
}

// ---------------- launch ----------------
extern "C" void kernel_launch(void* const* d_in, const int* in_sizes, int n_in,
                              void* d_out, int out_size) {
    const float* s_in      = (const float*)d_in[0];
    const float* e_in      = (const float*)d_in[1];
    const float* dst_feat  = (const float*)d_in[2];
    const float* fc_w      = (const float*)d_in[3];
    const float* dstfeat_w = (const float*)d_in[4];
    const float* proj_w    = (const float*)d_in[5];
    const float* proj_b    = (const float*)d_in[6];
    const float* ln_g      = (const float*)d_in[7];
    const float* ln_b      = (const float*)d_in[8];
    const float* w1        = (const float*)d_in[9];
    const float* b1        = (const float*)d_in[10];
    const float* w2        = (const float*)d_in[11];
    const float* b2        = (const float*)d_in[12];
    const int*   edge_src  = (const int*)d_in[13];
    const int*   edge_dst  = (const int*)d_in[14];
    float* out = (float*)d_out;

    float *zp, *dfp, *hp, *xp, *xnp, *tp, *wzp, *wdp;
    cudaGetSymbolAddress((void**)&zp,  g_z);
    cudaGetSymbolAddress((void**)&dfp, g_df);
    cudaGetSymbolAddress((void**)&hp,  g_h);
    cudaGetSymbolAddress((void**)&xp,  g_x);
    cudaGetSymbolAddress((void**)&xnp, g_xn);
    cudaGetSymbolAddress((void**)&tp,  g_t);
    cudaGetSymbolAddress((void**)&wzp, g_Wz);
    cudaGetSymbolAddress((void**)&wdp, g_Wd);

    const int TB = 256;
    dim3 gB(2, (NS + 127) / 128);

    // 1) repack per-head weights into plain [K, 256] matrices
    repack_w<<<(D * 256 + TB - 1) / TB, TB>>>(fc_w, wzp, D);
    repack_w<<<(FEAT * 256 + TB - 1) / TB, TB>>>(dstfeat_w, wdp, FEAT);

    // 2) z = e @ Wz  [NE,256]
    sgemm_k<0, false, false><<<dim3(2, (NE + 127) / 128), TB>>>(
        e_in, D, e_in, D, D, wzp, nullptr, nullptr, 0, zp, NE, 256, D);

    // 3) df = dst_feat @ Wd  [NS,256]
    sgemm_k<0, false, false><<<gB, TB>>>(
        dst_feat, FEAT, dst_feat, FEAT, FEAT, wdp, nullptr, nullptr, 0, dfp, NS, 256, FEAT);

    // 4) CSR build by dst (parallel decoupled scan)
    zero_counts<<<(NS + TB - 1) / TB, TB>>>();
    hist_kernel<<<(EDG + TB - 1) / TB, TB>>>(edge_dst);
    scan_pass1<<<NBLK, SCAN_B>>>();
    scan_pass2<<<1, 128>>>();
    scan_pass3<<<NBLK, SCAN_B>>>();
    scatter_kernel<<<(EDG + TB - 1) / TB, TB>>>(edge_src, edge_dst);

    // 5) attention + ELU -> g_h
    attn_kernel<<<(NS * 32 + TB - 1) / TB, TB>>>();

    // 6) proj: [h | s] @ proj_w + b -> g_x
    sgemm_k<0, true, false><<<gB, TB>>>(
        hp, 256, s_in, 256, 256, proj_w, proj_b, nullptr, 0, xp, NS, 256, 512);

    // 7) layernorm -> g_xn
    ln_kernel<<<(NS * 32 + TB - 1) / TB, TB>>>(xp, ln_g, ln_b, xnp);

    // 8) ffn1: gelu(xn @ w1 + b1) -> g_t
    sgemm_k<1, true, false><<<dim3(4, (NS + 127) / 128), TB>>>(
        xnp, 256, xnp, 256, 256, w1, b1, nullptr, 0, tp, NS, DFF, 256);

    // 9) ffn2: g_t @ w2 + b2 + g_x -> out
    sgemm_k<0, true, true><<<gB, TB>>>(
        tp, DFF, tp, DFF, DFF, w2, b2, xp, 256, out, NS, 256, DFF);
}

// round 7
// speedup vs baseline: 1.6769x; 1.6769x over previous
#include <cuda_runtime.h>
#include <cuda_bf16.h>
#include <cstdint>
#include <math.h>

// Problem constants (fixed by the dataset)
#define NS 100000
#define NE 100000
#define EDG 1600000
#define D 256
#define H 8
#define HD 32
#define FEAT 64
#define DFF 512

#define SCAN_B 1024
#define NBLK ((NS + SCAN_B - 1) / SCAN_B)   // 98
#define KPAD 40                              // bf16 elems per smem row (80B, 16B-aligned)

// ---------------- device scratch (no allocations allowed) ----------------
__device__ float g_z[(size_t)NE * D];
__device__ float g_df[(size_t)NS * D];
__device__ float g_h[(size_t)NS * D];
__device__ float g_x[(size_t)NS * D];
__device__ float g_xn[(size_t)NS * D];
__device__ float g_t[(size_t)NS * DFF];
__device__ float g_Wz[D * D];
__device__ float g_Wd[FEAT * D];
__device__ int   g_counts[NS];
__device__ int   g_offsets[NS + 1];
__device__ int   g_cursor[NS];
__device__ int   g_csr_src[EDG];
__device__ int   g_bsum[NBLK];

// ---------------- small helpers ----------------
__device__ __forceinline__ float gelu_fast(float x) {
    const float c = 0.7978845608028654f;
    float u = c * (x + 0.044715f * x * x * x);
    float e = __expf(2.0f * u);
    float th = 1.0f - 2.0f / (e + 1.0f);
    return 0.5f * x * (1.0f + th);
}

__device__ __forceinline__ uint32_t smem_u32(const void* p) {
    uint32_t a;
    asm("{ .reg .u64 t; cvta.to.shared.u64 t, %1; cvt.u32.u64 %0, t; }" : "=r"(a) : "l"(p));
    return a;
}

__device__ __forceinline__ void ldm_x4(uint32_t* r, uint32_t addr) {
    asm volatile("ldmatrix.sync.aligned.m8n8.x4.shared.b16 {%0,%1,%2,%3}, [%4];"
                 : "=r"(r[0]), "=r"(r[1]), "=r"(r[2]), "=r"(r[3]) : "r"(addr));
}

__device__ __forceinline__ void mma_bf16(float* c, const uint32_t* a, const uint32_t* b) {
    asm volatile(
        "mma.sync.aligned.m16n8k16.row.col.f32.bf16.bf16.f32 "
        "{%0,%1,%2,%3}, {%4,%5,%6,%7}, {%8,%9}, {%0,%1,%2,%3};"
        : "+f"(c[0]), "+f"(c[1]), "+f"(c[2]), "+f"(c[3])
        : "r"(a[0]), "r"(a[1]), "r"(a[2]), "r"(a[3]), "r"(b[0]), "r"(b[1]));
}

__device__ __forceinline__ void split_bf16(float x, __nv_bfloat16& hi, __nv_bfloat16& lo) {
    hi = __float2bfloat16_rn(x);
    lo = __float2bfloat16_rn(x - __bfloat162float(hi));
}

// ---------------- weight repack: (H, K, HD) -> [K, H*HD] ----------------
__global__ void repack_w(const float* __restrict__ w, float* __restrict__ out, int K) {
    int idx = blockIdx.x * blockDim.x + threadIdx.x;
    if (idx >= K * 256) return;
    int k = idx >> 8;
    int n = idx & 255;
    out[idx] = w[(n >> 5) * (K * 32) + k * 32 + (n & 31)];
}

// ================= tensor-core GEMM via mma.sync (bf16 3-product split) =================
// C[M, ldc] (tile 128x128/CTA) = act(A @ B + bias) + res.
// A rows: k < ksplit from A0 else A1 (k-tiles never straddle; ksplit % 32 == 0).
// B row-major [K, ldb]; n0..n0+127 must be in-range (N multiple of 128).
template <int ACT, bool BIAS, bool RES>
__global__ void __launch_bounds__(256, 2) mma_gemm(
    const float* __restrict__ A0, int lda0,
    const float* __restrict__ A1, int lda1, int ksplit,
    const float* __restrict__ B, int ldb,
    const float* __restrict__ bias,
    const float* __restrict__ res, int ldr,
    float* __restrict__ C, int ldc,
    int M, int K)
{
    __shared__ __nv_bfloat16 Ah[128 * KPAD];
    __shared__ __nv_bfloat16 Al[128 * KPAD];
    __shared__ __nv_bfloat16 Bh[128 * KPAD];
    __shared__ __nv_bfloat16 Bl[128 * KPAD];

    int t = threadIdx.x;
    int lane = t & 31, wid = t >> 5;
    int m0 = blockIdx.y * 128;
    int n0 = blockIdx.x * 128;
    int wm = wid & 3;    // 4 M-groups of 32 rows
    int wn = wid >> 2;   // 2 N-groups of 64 cols

    float acc[2][8][4];
#pragma unroll
    for (int i = 0; i < 2; i++)
#pragma unroll
        for (int j = 0; j < 8; j++)
#pragma unroll
            for (int q = 0; q < 4; q++) acc[i][j][q] = 0.0f;

    uint32_t sAh = smem_u32(Ah), sAl = smem_u32(Al);
    uint32_t sBh = smem_u32(Bh), sBl = smem_u32(Bl);

    // lane-fixed fragment offsets (bytes), k16-step adds ks*32
    uint32_t a_off = (uint32_t)(((wm * 32 + (lane & 15)) * KPAD + (lane >> 4) * 8) * 2);
    uint32_t b_off = (uint32_t)(((wn * 64 + (lane & 7) + (lane >> 4) * 8) * KPAD
                                 + ((lane >> 3) & 1) * 8) * 2);

    // A-load mapping: 2 threads per row, 16 k each
    int a_row = t >> 1;
    int a_kb  = (t & 1) * 16;
    bool a_ok = (m0 + a_row) < M;

    for (int k0 = 0; k0 < K; k0 += 32) {
        __syncthreads();
        // ---- A tile [128 m x 32 k] -> bf16 hi/lo ----
        {
            const float* Asrc; int lda, koff;
            if (k0 < ksplit) { Asrc = A0; lda = lda0; koff = k0; }
            else             { Asrc = A1; lda = lda1; koff = k0 - ksplit; }
            const float* ap = Asrc + (size_t)(m0 + a_row) * lda + koff + a_kb;
            int base = a_row * KPAD + a_kb;
#pragma unroll
            for (int i = 0; i < 4; i++) {
                float4 v = a_ok ? *(const float4*)(ap + i * 4)
                                : make_float4(0.f, 0.f, 0.f, 0.f);
                __nv_bfloat16 h, l;
                split_bf16(v.x, h, l); Ah[base + i*4 + 0] = h; Al[base + i*4 + 0] = l;
                split_bf16(v.y, h, l); Ah[base + i*4 + 1] = h; Al[base + i*4 + 1] = l;
                split_bf16(v.z, h, l); Ah[base + i*4 + 2] = h; Al[base + i*4 + 2] = l;
                split_bf16(v.w, h, l); Ah[base + i*4 + 3] = h; Al[base + i*4 + 3] = l;
            }
        }
        // ---- B tile: Bs[n][k] <- B[k0+k][n0+n], coalesced over n ----
        {
            int n = t & 127;
            int kk0 = t >> 7;  // 0 or 1
#pragma unroll
            for (int it = 0; it < 16; it++) {
                int k = kk0 + it * 2;
                float v = B[(size_t)(k0 + k) * ldb + n0 + n];
                __nv_bfloat16 h, l;
                split_bf16(v, h, l);
                Bh[n * KPAD + k] = h;
                Bl[n * KPAD + k] = l;
            }
        }
        __syncthreads();

        // ---- fragments + mma: 3 passes (Ah*Bh, Al*Bh, Ah*Bl) ----
#pragma unroll
        for (int ks = 0; ks < 2; ks++) {
            uint32_t koffb = (uint32_t)(ks * 32);
#pragma unroll
            for (int pass = 0; pass < 3; pass++) {
                uint32_t aBase = (pass == 1) ? sAl : sAh;
                uint32_t bBase = (pass == 2) ? sBl : sBh;
                uint32_t a[2][4];
                ldm_x4(a[0], aBase + a_off + koffb);
                ldm_x4(a[1], aBase + a_off + koffb + 16 * KPAD * 2);
                uint32_t b[4][4];
#pragma unroll
                for (int ni2 = 0; ni2 < 4; ni2++)
                    ldm_x4(b[ni2], bBase + b_off + koffb + ni2 * 16 * KPAD * 2);
#pragma unroll
                for (int mi = 0; mi < 2; mi++)
#pragma unroll
                    for (int ni = 0; ni < 8; ni++)
                        mma_bf16(acc[mi][ni], a[mi], &b[ni >> 1][(ni & 1) * 2]);
            }
        }
    }

    // ---- epilogue ----
#pragma unroll
    for (int mi = 0; mi < 2; mi++) {
#pragma unroll
        for (int ni = 0; ni < 8; ni++) {
            int cc = n0 + wn * 64 + ni * 8 + (lane & 3) * 2;
#pragma unroll
            for (int hh = 0; hh < 2; hh++) {
                int m = m0 + wm * 32 + mi * 16 + (lane >> 2) + hh * 8;
                if (m >= M) continue;
                float v0 = acc[mi][ni][hh * 2 + 0];
                float v1 = acc[mi][ni][hh * 2 + 1];
                if (BIAS) { v0 += bias[cc]; v1 += bias[cc + 1]; }
                if (ACT == 1) { v0 = gelu_fast(v0); v1 = gelu_fast(v1); }
                if (RES) {
                    const float* rp = res + (size_t)m * ldr + cc;
                    v0 += rp[0]; v1 += rp[1];
                }
                *(float2*)(C + (size_t)m * ldc + cc) = make_float2(v0, v1);
            }
        }
    }
}

// ---------------- CSR build ----------------
__global__ void zero_counts() {
    int i = blockIdx.x * blockDim.x + threadIdx.x;
    if (i < NS) g_counts[i] = 0;
}
__global__ void hist_kernel(const int* __restrict__ edge_dst) {
    int i = blockIdx.x * blockDim.x + threadIdx.x;
    if (i < EDG) atomicAdd(&g_counts[edge_dst[i]], 1);
}
__global__ void __launch_bounds__(SCAN_B) scan_pass1() {
    __shared__ int ws[32];
    int b = blockIdx.x, t = threadIdx.x;
    int i = b * SCAN_B + t;
    int v = (i < NS) ? g_counts[i] : 0;
#pragma unroll
    for (int o = 16; o; o >>= 1) v += __shfl_xor_sync(0xFFFFFFFFu, v, o);
    if ((t & 31) == 0) ws[t >> 5] = v;
    __syncthreads();
    if (t < 32) {
        int x = ws[t];
#pragma unroll
        for (int o = 16; o; o >>= 1) x += __shfl_xor_sync(0xFFFFFFFFu, x, o);
        if (t == 0) g_bsum[b] = x;
    }
}
__global__ void scan_pass2() {
    __shared__ int sh[128];
    int t = threadIdx.x;
    int orig = (t < NBLK) ? g_bsum[t] : 0;
    sh[t] = orig;
    __syncthreads();
    for (int o = 1; o < 128; o <<= 1) {
        int v = (t >= o) ? sh[t - o] : 0;
        __syncthreads();
        sh[t] += v;
        __syncthreads();
    }
    if (t < NBLK) g_bsum[t] = sh[t] - orig;
}
__global__ void __launch_bounds__(SCAN_B) scan_pass3() {
    __shared__ int ws[32];
    int b = blockIdx.x, t = threadIdx.x;
    int lane = t & 31, w = t >> 5;
    int i = b * SCAN_B + t;
    int v = (i < NS) ? g_counts[i] : 0;
    int x = v;
#pragma unroll
    for (int o = 1; o < 32; o <<= 1) {
        int y = __shfl_up_sync(0xFFFFFFFFu, x, o);
        if (lane >= o) x += y;
    }
    if (lane == 31) ws[w] = x;
    __syncthreads();
    if (w == 0) {
        int sv = ws[lane];
#pragma unroll
        for (int o = 1; o < 32; o <<= 1) {
            int y = __shfl_up_sync(0xFFFFFFFFu, sv, o);
            if (lane >= o) sv += y;
        }
        ws[lane] = sv;
    }
    __syncthreads();
    int incl = x + (w > 0 ? ws[w - 1] : 0) + g_bsum[b];
    if (i < NS) {
        g_offsets[i + 1] = incl;
        g_cursor[i] = incl - v;
    }
    if (b == 0 && t == 0) g_offsets[0] = 0;
}
__global__ void scatter_kernel(const int* __restrict__ edge_src,
                               const int* __restrict__ edge_dst) {
    int i = blockIdx.x * blockDim.x + threadIdx.x;
    if (i >= EDG) return;
    int dst = edge_dst[i];
    int pos = atomicAdd(&g_cursor[dst], 1);
    g_csr_src[pos] = edge_src[i];
}

// ---------------- attention: warp per dst, lane = (head, quarter) (R4 winner) ----------------
__global__ void __launch_bounds__(256) attn_kernel() {
    int gw = (blockIdx.x * blockDim.x + threadIdx.x) >> 5;
    if (gw >= NS) return;
    int lane = threadIdx.x & 31;
    int off = (lane >> 2) * 32 + (lane & 3) * 8;

    int beg = g_offsets[gw];
    int end = g_offsets[gw + 1];

    const float* dfp = g_df + (size_t)gw * 256 + off;
    float4 d0 = *(const float4*)(dfp);
    float4 d1 = *(const float4*)(dfp + 4);

    float m = -1e30f, den = 0.0f;
    float4 a0 = make_float4(0.f, 0.f, 0.f, 0.f);
    float4 a1 = make_float4(0.f, 0.f, 0.f, 0.f);

    int e = beg;
    for (; e + 2 <= end; e += 2) {
        int s0 = __ldg(&g_csr_src[e]);
        int s1 = __ldg(&g_csr_src[e + 1]);
        const float* zp0 = g_z + (size_t)s0 * 256 + off;
        const float* zp1 = g_z + (size_t)s1 * 256 + off;
        float4 x0 = __ldg((const float4*)zp0);
        float4 x1 = __ldg((const float4*)(zp0 + 4));
        float4 y0 = __ldg((const float4*)zp1);
        float4 y1 = __ldg((const float4*)(zp1 + 4));

        float sa = x0.x * d0.x + x0.y * d0.y + x0.z * d0.z + x0.w * d0.w
                 + x1.x * d1.x + x1.y * d1.y + x1.z * d1.z + x1.w * d1.w;
        float sb = y0.x * d0.x + y0.y * d0.y + y0.z * d0.z + y0.w * d0.w
                 + y1.x * d1.x + y1.y * d1.y + y1.z * d1.z + y1.w * d1.w;
        sa += __shfl_xor_sync(0xFFFFFFFFu, sa, 1);
        sb += __shfl_xor_sync(0xFFFFFFFFu, sb, 1);
        sa += __shfl_xor_sync(0xFFFFFFFFu, sa, 2);
        sb += __shfl_xor_sync(0xFFFFFFFFu, sb, 2);

        {
            float mn = fmaxf(m, sa);
            float sc = __expf(m - mn);
            float w  = __expf(sa - mn);
            den = den * sc + w;
            a0.x = a0.x * sc + w * x0.x; a0.y = a0.y * sc + w * x0.y;
            a0.z = a0.z * sc + w * x0.z; a0.w = a0.w * sc + w * x0.w;
            a1.x = a1.x * sc + w * x1.x; a1.y = a1.y * sc + w * x1.y;
            a1.z = a1.z * sc + w * x1.z; a1.w = a1.w * sc + w * x1.w;
            m = mn;
        }
        {
            float mn = fmaxf(m, sb);
            float sc = __expf(m - mn);
            float w  = __expf(sb - mn);
            den = den * sc + w;
            a0.x = a0.x * sc + w * y0.x; a0.y = a0.y * sc + w * y0.y;
            a0.z = a0.z * sc + w * y0.z; a0.w = a0.w * sc + w * y0.w;
            a1.x = a1.x * sc + w * y1.x; a1.y = a1.y * sc + w * y1.y;
            a1.z = a1.z * sc + w * y1.z; a1.w = a1.w * sc + w * y1.w;
            m = mn;
        }
    }
    for (; e < end; e++) {
        int s0 = __ldg(&g_csr_src[e]);
        const float* zp0 = g_z + (size_t)s0 * 256 + off;
        float4 x0 = __ldg((const float4*)zp0);
        float4 x1 = __ldg((const float4*)(zp0 + 4));
        float sa = x0.x * d0.x + x0.y * d0.y + x0.z * d0.z + x0.w * d0.w
                 + x1.x * d1.x + x1.y * d1.y + x1.z * d1.z + x1.w * d1.w;
        sa += __shfl_xor_sync(0xFFFFFFFFu, sa, 1);
        sa += __shfl_xor_sync(0xFFFFFFFFu, sa, 2);
        float mn = fmaxf(m, sa);
        float sc = __expf(m - mn);
        float w  = __expf(sa - mn);
        den = den * sc + w;
        a0.x = a0.x * sc + w * x0.x; a0.y = a0.y * sc + w * x0.y;
        a0.z = a0.z * sc + w * x0.z; a0.w = a0.w * sc + w * x0.w;
        a1.x = a1.x * sc + w * x1.x; a1.y = a1.y * sc + w * x1.y;
        a1.z = a1.z * sc + w * x1.z; a1.w = a1.w * sc + w * x1.w;
        m = mn;
    }

    float inv = 1.0f / den;
    float v[8];
    v[0] = a0.x * inv; v[1] = a0.y * inv; v[2] = a0.z * inv; v[3] = a0.w * inv;
    v[4] = a1.x * inv; v[5] = a1.y * inv; v[6] = a1.z * inv; v[7] = a1.w * inv;
#pragma unroll
    for (int i = 0; i < 8; i++)
        v[i] = (v[i] > 0.0f) ? v[i] : expm1f(v[i]);  // ELU(alpha=1)

    float* hp = g_h + (size_t)gw * 256 + off;
    *(float4*)(hp)     = make_float4(v[0], v[1], v[2], v[3]);
    *(float4*)(hp + 4) = make_float4(v[4], v[5], v[6], v[7]);
}

// ---------------- layernorm: one warp per row ----------------
__global__ void ln_kernel(const float* __restrict__ x,
                          const float* __restrict__ gam,
                          const float* __restrict__ bet,
                          float* __restrict__ y) {
    int row = (blockIdx.x * blockDim.x + threadIdx.x) >> 5;
    if (row >= NS) return;
    int lane = threadIdx.x & 31;
    const float* xp = x + (size_t)row * 256;
    float v[8];
    float s = 0.0f, s2 = 0.0f;
#pragma unroll
    for (int r = 0; r < 8; r++) {
        v[r] = xp[r * 32 + lane];
        s += v[r];
        s2 += v[r] * v[r];
    }
#pragma unroll
    for (int off = 16; off > 0; off >>= 1) {
        s  += __shfl_xor_sync(0xFFFFFFFFu, s, off);
        s2 += __shfl_xor_sync(0xFFFFFFFFu, s2, off);
    }
    float mean = s * (1.0f / 256.0f);
    float var = s2 * (1.0f / 256.0f) - mean * mean;
    float inv = rsqrtf(var + 1e-6f);
    float* yp = y + (size_t)row * 256;
#pragma unroll
    for (int r = 0; r < 8; r++) {
        int c = r * 32 + lane;
        yp[c] = (v[r] - mean) * inv * gam[c] + bet[c];
    }
}

// ---------------- launch ----------------
extern "C" void kernel_launch(void* const* d_in, const int* in_sizes, int n_in,
                              void* d_out, int out_size) {
    const float* s_in      = (const float*)d_in[0];
    const float* e_in      = (const float*)d_in[1];
    const float* dst_feat  = (const float*)d_in[2];
    const float* fc_w      = (const float*)d_in[3];
    const float* dstfeat_w = (const float*)d_in[4];
    const float* proj_w    = (const float*)d_in[5];
    const float* proj_b    = (const float*)d_in[6];
    const float* ln_g      = (const float*)d_in[7];
    const float* ln_b      = (const float*)d_in[8];
    const float* w1        = (const float*)d_in[9];
    const float* b1        = (const float*)d_in[10];
    const float* w2        = (const float*)d_in[11];
    const float* b2        = (const float*)d_in[12];
    const int*   edge_src  = (const int*)d_in[13];
    const int*   edge_dst  = (const int*)d_in[14];
    float* out = (float*)d_out;

    float *zp, *dfp, *hp, *xp, *xnp, *tp, *wzp, *wdp;
    cudaGetSymbolAddress((void**)&zp,  g_z);
    cudaGetSymbolAddress((void**)&dfp, g_df);
    cudaGetSymbolAddress((void**)&hp,  g_h);
    cudaGetSymbolAddress((void**)&xp,  g_x);
    cudaGetSymbolAddress((void**)&xnp, g_xn);
    cudaGetSymbolAddress((void**)&tp,  g_t);
    cudaGetSymbolAddress((void**)&wzp, g_Wz);
    cudaGetSymbolAddress((void**)&wdp, g_Wd);

    const int TB = 256;
    const int MB = (NS + 127) / 128;  // 782

    // 1) repack per-head weights into plain [K, 256] matrices
    repack_w<<<(D * 256 + TB - 1) / TB, TB>>>(fc_w, wzp, D);
    repack_w<<<(FEAT * 256 + TB - 1) / TB, TB>>>(dstfeat_w, wdp, FEAT);

    // 2) z = e @ Wz  [NE,256]
    mma_gemm<0, false, false><<<dim3(2, MB), TB>>>(
        e_in, D, e_in, D, D, wzp, 256, nullptr, nullptr, 0, zp, 256, NE, 256);

    // 3) df = dst_feat @ Wd  [NS,256]
    mma_gemm<0, false, false><<<dim3(2, MB), TB>>>(
        dst_feat, FEAT, dst_feat, FEAT, FEAT, wdp, 256, nullptr, nullptr, 0, dfp, 256, NS, 64);

    // 4) CSR build by dst (parallel decoupled scan)
    zero_counts<<<(NS + TB - 1) / TB, TB>>>();
    hist_kernel<<<(EDG + TB - 1) / TB, TB>>>(edge_dst);
    scan_pass1<<<NBLK, SCAN_B>>>();
    scan_pass2<<<1, 128>>>();
    scan_pass3<<<NBLK, SCAN_B>>>();
    scatter_kernel<<<(EDG + TB - 1) / TB, TB>>>(edge_src, edge_dst);

    // 5) attention + ELU -> g_h
    attn_kernel<<<(NS * 32 + TB - 1) / TB, TB>>>();

    // 6) proj: [h | s] @ proj_w + b -> g_x
    mma_gemm<0, true, false><<<dim3(2, MB), TB>>>(
        hp, 256, s_in, 256, 256, proj_w, 256, proj_b, nullptr, 0, xp, 256, NS, 512);

    // 7) layernorm -> g_xn
    ln_kernel<<<(NS * 32 + TB - 1) / TB, TB>>>(xp, ln_g, ln_b, xnp);

    // 8) ffn1: gelu(xn @ w1 + b1) -> g_t
    mma_gemm<1, true, false><<<dim3(4, MB), TB>>>(
        xnp, 256, xnp, 256, 256, w1, 512, b1, nullptr, 0, tp, 512, NS, 256);

    // 9) ffn2: g_t @ w2 + b2 + g_x -> out
    mma_gemm<0, true, true><<<dim3(2, MB), TB>>>(
        tp, DFF, tp, DFF, DFF, w2, 256, b2, xp, 256, out, 256, NS, 512);
}